// round 10
// baseline (speedup 1.0000x reference)
#include <cuda_runtime.h>
#include <cuda_bf16.h>
#include <cstdint>

typedef __nv_bfloat16 bf16;

#define BATCH 2
#define SEQ 2048
#define DMODEL 768
#define NH 12
#define DKH 64
#define MROWS (BATCH*SEQ)

// ---------------- scratch (no allocs allowed) ----------------
__device__ __align__(16) bf16 g_xhi[3u*MROWS*DMODEL];
__device__ __align__(16) bf16 g_xlo[3u*MROWS*DMODEL];
__device__ __align__(16) bf16 g_whi[4u*DMODEL*DMODEL];
__device__ __align__(16) bf16 g_wlo[4u*DMODEL*DMODEL];
__device__ __align__(16) bf16 g_qhi[MROWS*DMODEL];
__device__ __align__(16) bf16 g_qlo[MROWS*DMODEL];
__device__ __align__(16) bf16 g_khi[MROWS*DMODEL];
__device__ __align__(16) bf16 g_klo[MROWS*DMODEL];
__device__ __align__(16) bf16 g_vhi[MROWS*DMODEL];
__device__ __align__(16) bf16 g_vlo[MROWS*DMODEL];
__device__ __align__(16) bf16 g_chi[MROWS*DMODEL];
__device__ __align__(16) bf16 g_clo[MROWS*DMODEL];
__device__ __align__(16) bf16 g_mbias[(size_t)SEQ*SEQ];

// exp(x*0.125 + b) = exp2(x*C + b*LOG2E), C = 0.125*log2(e)
#define SCALE_LOG2E 0.18033688011112042f
#define NEG_BIAS   (-1.4426950408889634e9f)

// ---------------- helpers ----------------
__device__ __forceinline__ uint32_t smem_u32(const void* p) {
    uint32_t a;
    asm("{ .reg .u64 t; cvta.to.shared.u64 t, %1; cvt.u32.u64 %0, t; }" : "=r"(a) : "l"(p));
    return a;
}
__device__ __forceinline__ void ldsm4(uint32_t r[4], uint32_t a) {
    asm volatile("ldmatrix.sync.aligned.m8n8.x4.shared.b16 {%0,%1,%2,%3}, [%4];"
        : "=r"(r[0]), "=r"(r[1]), "=r"(r[2]), "=r"(r[3]) : "r"(a));
}
__device__ __forceinline__ void ldsm4t(uint32_t r[4], uint32_t a) {
    asm volatile("ldmatrix.sync.aligned.m8n8.x4.trans.shared.b16 {%0,%1,%2,%3}, [%4];"
        : "=r"(r[0]), "=r"(r[1]), "=r"(r[2]), "=r"(r[3]) : "r"(a));
}
__device__ __forceinline__ void mma16816(float c[4], uint32_t a0, uint32_t a1, uint32_t a2, uint32_t a3,
                                         uint32_t b0, uint32_t b1) {
    asm volatile("mma.sync.aligned.m16n8k16.row.col.f32.bf16.bf16.f32 "
        "{%0,%1,%2,%3}, {%4,%5,%6,%7}, {%8,%9}, {%0,%1,%2,%3};"
        : "+f"(c[0]), "+f"(c[1]), "+f"(c[2]), "+f"(c[3])
        : "r"(a0), "r"(a1), "r"(a2), "r"(a3), "r"(b0), "r"(b1));
}
__device__ __forceinline__ uint32_t packbf(float x0, float x1) {
    uint32_t r;
    asm("cvt.rn.bf16x2.f32 %0, %1, %2;" : "=r"(r) : "f"(x1), "f"(x0));
    return r;
}
__device__ __forceinline__ void hilo(float v, float& h, float& l) {
    h = __bfloat162float(__float2bfloat16_rn(v));
    l = v - h;
}
__device__ __forceinline__ void cpa16(uint32_t s, const void* g) {
    asm volatile("cp.async.cg.shared.global [%0], [%1], 16;" :: "r"(s), "l"(g) : "memory");
}
#define CP_COMMIT() asm volatile("cp.async.commit_group;" ::: "memory")
#define CP_WAIT0()  asm volatile("cp.async.wait_group 0;" ::: "memory")

// ---------------- conversion kernels ----------------
__global__ __launch_bounds__(256) void cvt_in_kernel(
    const float* __restrict__ q, const float* __restrict__ k, const float* __restrict__ v)
{
    const float* src = blockIdx.z == 0 ? q : blockIdx.z == 1 ? k : v;
    bf16* hi = g_xhi + (size_t)blockIdx.z * MROWS * DMODEL;
    bf16* lo = g_xlo + (size_t)blockIdx.z * MROWS * DMODEL;
    size_t i = ((size_t)blockIdx.x * 256 + threadIdx.x) * 4;
    float4 f = *(const float4*)(src + i);
    float h0,l0,h1,l1,h2,l2,h3,l3;
    hilo(f.x,h0,l0); hilo(f.y,h1,l1); hilo(f.z,h2,l2); hilo(f.w,h3,l3);
    *(uint2*)(hi + i) = make_uint2(packbf(f.x, f.y), packbf(f.z, f.w));
    *(uint2*)(lo + i) = make_uint2(packbf(l0, l1), packbf(l2, l3));
}

__global__ __launch_bounds__(256) void cvt_w_kernel(
    const float* __restrict__ wq, const float* __restrict__ wk,
    const float* __restrict__ wv, const float* __restrict__ wo)
{
    const float* src = blockIdx.z == 0 ? wq : blockIdx.z == 1 ? wk : blockIdx.z == 2 ? wv : wo;
    bf16* hi = g_whi + (size_t)blockIdx.z * DMODEL * DMODEL;
    bf16* lo = g_wlo + (size_t)blockIdx.z * DMODEL * DMODEL;
    size_t i = ((size_t)blockIdx.x * 256 + threadIdx.x) * 4;
    float4 f = *(const float4*)(src + i);
    float h0,l0,h1,l1,h2,l2,h3,l3;
    hilo(f.x,h0,l0); hilo(f.y,h1,l1); hilo(f.z,h2,l2); hilo(f.w,h3,l3);
    *(uint2*)(hi + i) = make_uint2(packbf(f.x, f.y), packbf(f.z, f.w));
    *(uint2*)(lo + i) = make_uint2(packbf(l0, l1), packbf(l2, l3));
}

// store mask bias pre-multiplied by log2(e): 0 or -1e9*log2e
__global__ __launch_bounds__(256) void cvt_mask_kernel(const int* __restrict__ mask)
{
    size_t i = ((size_t)blockIdx.x * 256 + threadIdx.x) * 4;
    int4 m = *(const int4*)(mask + i);
    float v0 = m.x ? 0.0f : NEG_BIAS;
    float v1 = m.y ? 0.0f : NEG_BIAS;
    float v2 = m.z ? 0.0f : NEG_BIAS;
    float v3 = m.w ? 0.0f : NEG_BIAS;
    *(uint2*)(g_mbias + i) = make_uint2(packbf(v0, v1), packbf(v2, v3));
}

// ---------------- GEMM: smem double-buffered, register-prefetch pipeline ----------------
#define HS 40                       // smem row stride in halfs (32 + 8 pad)
#define GTB (128*HS*2)              // bytes per tile (10240)
#define GSTAGE (4*GTB)              // Ahi, Alo, Bhi, Blo per stage (40960)
#define GEMM_SMEM (2*GSTAGE)        // 81920 B

template<bool OUT>
__global__ __launch_bounds__(256, 1) void gemm_mma_kernel(
    const float* __restrict__ bq, const float* __restrict__ bk,
    const float* __restrict__ bv, const float* __restrict__ bo,
    float* __restrict__ outp)
{
    extern __shared__ char smc[];
    const uint32_t sb = smem_u32(smc);
    const int t = threadIdx.x, lane = t & 31, wid = t >> 5;
    const int wm = wid >> 2, wn = wid & 3;
    const int z = OUT ? 3 : blockIdx.z;

    const bf16 *Ahi, *Alo;
    if (OUT) { Ahi = g_chi; Alo = g_clo; }
    else { Ahi = g_xhi + (size_t)z*MROWS*DMODEL; Alo = g_xlo + (size_t)z*MROWS*DMODEL; }
    const bf16* Bhi = g_whi + (size_t)z*DMODEL*DMODEL;
    const bf16* Blo = g_wlo + (size_t)z*DMODEL*DMODEL;
    const float* bias = OUT ? bo : (z == 0 ? bq : z == 1 ? bk : bv);

    const int bm = blockIdx.y * 128;
    const int bn = blockIdx.x * 128;

    float acc[4][4][4] = {};

    const int lrow0 = t >> 2, lch = t & 3;
    const bf16* srcs[4] = {Ahi, Alo, Bhi, Blo};
    uint4 buf[4][2];

    auto ldg_chunk = [&](int c) {
        const int k0 = c * 32;
        #pragma unroll
        for (int tt = 0; tt < 4; tt++) {
            int rb = (tt < 2) ? bm : bn;
            #pragma unroll
            for (int u = 0; u < 2; u++)
                buf[tt][u] = *(const uint4*)(srcs[tt] + (size_t)(rb + lrow0 + 64*u)*DMODEL + k0 + lch*8);
        }
    };
    auto sts_chunk = [&](int stage) {
        #pragma unroll
        for (int tt = 0; tt < 4; tt++)
            #pragma unroll
            for (int u = 0; u < 2; u++)
                *(uint4*)(smc + stage*GSTAGE + tt*GTB + ((lrow0 + 64*u)*HS + lch*8)*2) = buf[tt][u];
    };

    // prologue: chunk0 -> stage0; chunk1 -> regs
    ldg_chunk(0);
    sts_chunk(0);
    ldg_chunk(1);
    __syncthreads();

    for (int c = 0; c < 24; c++) {
        // overlap: store next chunk to the other stage, prefetch chunk+2, then MMAs
        if (c < 23) sts_chunk((c + 1) & 1);
        if (c < 22) ldg_chunk(c + 2);

        const uint32_t stb = sb + (c & 1) * GSTAGE;
        #pragma unroll
        for (int ks = 0; ks < 2; ks++) {
            uint32_t ah[4][4], al[4][4];
            #pragma unroll
            for (int am = 0; am < 4; am++) {
                uint32_t ad = stb + ((64*wm + 16*am + (lane & 15))*HS + 16*ks + (lane >> 4)*8)*2;
                ldsm4(ah[am], ad);
                ldsm4(al[am], ad + GTB);
            }
            #pragma unroll
            for (int bp = 0; bp < 2; bp++) {
                uint32_t bd = stb + 2*GTB +
                    ((32*wn + 16*bp + (lane & 7) + ((lane >> 4) & 1)*8)*HS + 16*ks + ((lane >> 3) & 1)*8)*2;
                uint32_t bh[4], bl[4];
                ldsm4(bh, bd);
                ldsm4(bl, bd + GTB);
                #pragma unroll
                for (int fi = 0; fi < 2; fi++) {
                    const int bf_ = 2*bp + fi;
                    #pragma unroll
                    for (int am = 0; am < 4; am++) {
                        mma16816(acc[am][bf_], ah[am][0], ah[am][1], ah[am][2], ah[am][3], bh[2*fi], bh[2*fi+1]);
                        mma16816(acc[am][bf_], ah[am][0], ah[am][1], ah[am][2], ah[am][3], bl[2*fi], bl[2*fi+1]);
                        mma16816(acc[am][bf_], al[am][0], al[am][1], al[am][2], al[am][3], bh[2*fi], bh[2*fi+1]);
                    }
                }
            }
        }
        __syncthreads();
    }

    // epilogue
    const int rg = lane >> 2, cq = lane & 3;
    bf16* Dhi = z == 0 ? g_qhi : z == 1 ? g_khi : g_vhi;
    bf16* Dlo = z == 0 ? g_qlo : z == 1 ? g_klo : g_vlo;
    #pragma unroll
    for (int am = 0; am < 4; am++) {
        const int m1 = bm + 64*wm + 16*am + rg;
        const int m2 = m1 + 8;
        #pragma unroll
        for (int bf_ = 0; bf_ < 4; bf_++) {
            const int n = bn + 32*wn + 8*bf_ + 2*cq;
            const float bb0 = bias[n], bb1 = bias[n+1];
            float v00 = acc[am][bf_][0] + bb0, v01 = acc[am][bf_][1] + bb1;
            float v10 = acc[am][bf_][2] + bb0, v11 = acc[am][bf_][3] + bb1;
            if (OUT) {
                *(float2*)(outp + (size_t)m1*DMODEL + n) = make_float2(v00, v01);
                *(float2*)(outp + (size_t)m2*DMODEL + n) = make_float2(v10, v11);
            } else {
                const int hh = n >> 6, d = n & 63;
                const int b1_ = m1 >> 11, s1_ = m1 & (SEQ-1);
                const int b2_ = m2 >> 11, s2_ = m2 & (SEQ-1);
                size_t i1 = ((size_t)(b1_*NH + hh)*SEQ + s1_)*DKH + d;
                size_t i2 = ((size_t)(b2_*NH + hh)*SEQ + s2_)*DKH + d;
                float h0,l0,h1,l1;
                hilo(v00,h0,l0); hilo(v01,h1,l1);
                *(uint32_t*)(Dhi + i1) = packbf(v00, v01);
                *(uint32_t*)(Dlo + i1) = packbf(l0, l1);
                hilo(v10,h0,l0); hilo(v11,h1,l1);
                *(uint32_t*)(Dhi + i2) = packbf(v10, v11);
                *(uint32_t*)(Dlo + i2) = packbf(l0, l1);
            }
        }
    }
}

// ---------------- flash attention: no-max softmax, 64 q-rows, 128 threads ----------------
#define VS 72                        // smem row stride in halfs (64 + 8 pad)
#define QTB (64*VS*2)                // 9216 B per 64-row tile
#define KVSTG (4*QTB)                // Khi Klo Vhi Vlo = 36864 B
#define ATTN_SMEM (2*QTB + 2*KVSTG)  // 92160 B

__global__ __launch_bounds__(128, 2) void attn_mma_kernel()
{
    extern __shared__ char smc[];
    const uint32_t sb = smem_u32(smc);
    const uint32_t kvb = sb + 2*QTB;
    const int t = threadIdx.x, lane = t & 31, wid = t >> 5;
    const int rg = lane >> 2, cq = lane & 3;
    const int q0 = blockIdx.x * 64;
    const int h  = blockIdx.y;
    const int b_ = blockIdx.z;
    const size_t headoff = (size_t)(b_*NH + h) * SEQ * DKH;

    auto kvpre = [&](int kt, int s) {
        #pragma unroll
        for (int u = 0; u < 4; u++) {
            int idx = t + 128*u, row = idx >> 3, ch = idx & 7;
            size_t g = headoff + (size_t)(kt*64 + row)*DKH + ch*8;
            uint32_t so = kvb + s*KVSTG + (row*VS + ch*8)*2;
            cpa16(so + 0*QTB, g_khi + g);
            cpa16(so + 1*QTB, g_klo + g);
            cpa16(so + 2*QTB, g_vhi + g);
            cpa16(so + 3*QTB, g_vlo + g);
        }
    };

    kvpre(0, 0); CP_COMMIT();

    // load Q tile (hi, lo) once
    #pragma unroll
    for (int u = 0; u < 4; u++) {
        int idx = t + 128*u, row = idx >> 3, ch = idx & 7;
        size_t g = headoff + (size_t)(q0 + row)*DKH + ch*8;
        uint32_t so = (row*VS + ch*8)*2;
        *(uint4*)(smc + 0*QTB + so) = *(const uint4*)(g_qhi + g);
        *(uint4*)(smc + 1*QTB + so) = *(const uint4*)(g_qlo + g);
    }
    __syncthreads();

    // hoist Q fragments (warp owns q rows [16*wid, 16*wid+16))
    uint32_t qh[4][4], ql[4][4];
    #pragma unroll
    for (int ks = 0; ks < 4; ks++) {
        uint32_t qa = sb + ((16*wid + (lane & 15))*VS + 16*ks + (lane >> 4)*8)*2;
        ldsm4(qh[ks], qa);
        ldsm4(ql[ks], qa + QTB);
    }

    float o[8][4] = {};
    float lsum1 = 0.0f, lsum2 = 0.0f;   // unnormalized row sums (partial, per-thread)

    const bf16* mb1 = g_mbias + (size_t)(q0 + 16*wid + rg)*SEQ + 2*cq;
    const bf16* mb2 = mb1 + 8*SEQ;

    for (int kt = 0; kt < 32; kt++) {
        CP_WAIT0();
        __syncthreads();
        if (kt < 31) { kvpre(kt + 1, (kt + 1) & 1); CP_COMMIT(); }

        const uint32_t stb = kvb + (kt & 1)*KVSTG;

        // S = Q K^T   (16 q x 64 k per warp)
        float s[8][4] = {};
        #pragma unroll
        for (int ks = 0; ks < 4; ks++) {
            #pragma unroll
            for (int fp = 0; fp < 4; fp++) {
                uint32_t kd = stb +
                    ((16*fp + (lane & 7) + ((lane >> 4) & 1)*8)*VS + 16*ks + ((lane >> 3) & 1)*8)*2;
                uint32_t kh[4], kl[4];
                ldsm4(kh, kd);
                ldsm4(kl, kd + QTB);
                #pragma unroll
                for (int fi = 0; fi < 2; fi++) {
                    const int f = 2*fp + fi;
                    mma16816(s[f], qh[ks][0], qh[ks][1], qh[ks][2], qh[ks][3], kh[2*fi], kh[2*fi+1]);
                    mma16816(s[f], qh[ks][0], qh[ks][1], qh[ks][2], qh[ks][3], kl[2*fi], kl[2*fi+1]);
                    mma16816(s[f], ql[ks][0], ql[ks][1], ql[ks][2], ql[ks][3], kh[2*fi], kh[2*fi+1]);
                }
            }
        }

        // p = exp2(raw*C + premultiplied_bias) ; no max tracking, no rescale
        #pragma unroll
        for (int f = 0; f < 8; f++) {
            __nv_bfloat162 u1 = *(const __nv_bfloat162*)(mb1 + kt*64 + 8*f);
            __nv_bfloat162 u2 = *(const __nv_bfloat162*)(mb2 + kt*64 + 8*f);
            s[f][0] = exp2f(fmaf(s[f][0], SCALE_LOG2E, __low2float(u1)));
            s[f][1] = exp2f(fmaf(s[f][1], SCALE_LOG2E, __high2float(u1)));
            s[f][2] = exp2f(fmaf(s[f][2], SCALE_LOG2E, __low2float(u2)));
            s[f][3] = exp2f(fmaf(s[f][3], SCALE_LOG2E, __high2float(u2)));
            lsum1 += s[f][0] + s[f][1];
            lsum2 += s[f][2] + s[f][3];
        }

        // O += P @ V   (16 q x 64 k  times  64 k x 64 d), P split hi/lo
        #pragma unroll
        for (int kk = 0; kk < 4; kk++) {
            float* p = s[2*kk];
            float* q = s[2*kk+1];
            float h0,l0,h1,l1v;
            uint32_t a0h = packbf(p[0], p[1]);
            hilo(p[0],h0,l0); hilo(p[1],h1,l1v);
            uint32_t a0l = packbf(l0, l1v);
            uint32_t a1h = packbf(p[2], p[3]);
            hilo(p[2],h0,l0); hilo(p[3],h1,l1v);
            uint32_t a1l = packbf(l0, l1v);
            uint32_t a2h = packbf(q[0], q[1]);
            hilo(q[0],h0,l0); hilo(q[1],h1,l1v);
            uint32_t a2l = packbf(l0, l1v);
            uint32_t a3h = packbf(q[2], q[3]);
            hilo(q[2],h0,l0); hilo(q[3],h1,l1v);
            uint32_t a3l = packbf(l0, l1v);

            #pragma unroll
            for (int dg = 0; dg < 4; dg++) {
                uint32_t vd = stb + 2*QTB + ((16*kk + (lane & 15))*VS + 16*dg + (lane >> 4)*8)*2;
                uint32_t vh[4], vl[4];
                ldsm4t(vh, vd);
                ldsm4t(vl, vd + QTB);
                #pragma unroll
                for (int fi = 0; fi < 2; fi++) {
                    const int df = 2*dg + fi;
                    mma16816(o[df], a0h, a1h, a2h, a3h, vh[2*fi], vh[2*fi+1]);
                    mma16816(o[df], a0h, a1h, a2h, a3h, vl[2*fi], vl[2*fi+1]);
                    mma16816(o[df], a0l, a1l, a2l, a3l, vh[2*fi], vh[2*fi+1]);
                }
            }
        }
    }

    // one final reduction of the row sums across the 4 quad lanes
    lsum1 += __shfl_xor_sync(0xffffffffu, lsum1, 1);
    lsum1 += __shfl_xor_sync(0xffffffffu, lsum1, 2);
    lsum2 += __shfl_xor_sync(0xffffffffu, lsum2, 1);
    lsum2 += __shfl_xor_sync(0xffffffffu, lsum2, 2);

    // epilogue: normalize, split hi/lo, write ctx
    const float inv1 = 1.0f / lsum1, inv2 = 1.0f / lsum2;
    const int gr1 = q0 + 16*wid + rg;
    size_t base1 = ((size_t)b_*SEQ + gr1)*DMODEL + h*DKH;
    size_t base2 = base1 + (size_t)8*DMODEL;
    #pragma unroll
    for (int df = 0; df < 8; df++) {
        const int d0 = 8*df + 2*cq;
        float v0 = o[df][0]*inv1, v1 = o[df][1]*inv1;
        float v2 = o[df][2]*inv2, v3 = o[df][3]*inv2;
        float h0,l0,h1,l1v;
        hilo(v0,h0,l0); hilo(v1,h1,l1v);
        *(uint32_t*)(g_chi + base1 + d0) = packbf(v0, v1);
        *(uint32_t*)(g_clo + base1 + d0) = packbf(l0, l1v);
        hilo(v2,h0,l0); hilo(v3,h1,l1v);
        *(uint32_t*)(g_chi + base2 + d0) = packbf(v2, v3);
        *(uint32_t*)(g_clo + base2 + d0) = packbf(l0, l1v);
    }
}

// ---------------- launcher ----------------
extern "C" void kernel_launch(void* const* d_in, const int* in_sizes, int n_in,
                              void* d_out, int out_size)
{
    const float* q   = (const float*)d_in[0];
    const float* k   = (const float*)d_in[1];
    const float* v   = (const float*)d_in[2];
    const int*   msk = (const int*)  d_in[3];
    const float* w_q = (const float*)d_in[4];
    const float* b_q = (const float*)d_in[5];
    const float* w_k = (const float*)d_in[6];
    const float* b_k = (const float*)d_in[7];
    const float* w_v = (const float*)d_in[8];
    const float* b_v = (const float*)d_in[9];
    const float* w_o = (const float*)d_in[10];
    const float* b_o = (const float*)d_in[11];
    float* out = (float*)d_out;

    cudaFuncSetAttribute(gemm_mma_kernel<false>, cudaFuncAttributeMaxDynamicSharedMemorySize, GEMM_SMEM);
    cudaFuncSetAttribute(gemm_mma_kernel<true>,  cudaFuncAttributeMaxDynamicSharedMemorySize, GEMM_SMEM);
    cudaFuncSetAttribute(attn_mma_kernel, cudaFuncAttributeMaxDynamicSharedMemorySize, ATTN_SMEM);

    cvt_in_kernel<<<dim3(MROWS*DMODEL/1024, 1, 3), 256>>>(q, k, v);
    cvt_w_kernel<<<dim3(DMODEL*DMODEL/1024, 1, 4), 256>>>(w_q, w_k, w_v, w_o);
    cvt_mask_kernel<<<dim3((size_t)SEQ*SEQ/1024, 1, 1), 256>>>(msk);
    gemm_mma_kernel<false><<<dim3(DMODEL/128, MROWS/128, 3), 256, GEMM_SMEM>>>(b_q, b_k, b_v, b_o, out);
    attn_mma_kernel<<<dim3(SEQ/64, NH, BATCH), 128, ATTN_SMEM>>>();
    gemm_mma_kernel<true><<<dim3(DMODEL/128, MROWS/128, 1), 256, GEMM_SMEM>>>(b_q, b_k, b_v, b_o, out);
}

// round 11
// speedup vs baseline: 1.0545x; 1.0545x over previous
#include <cuda_runtime.h>
#include <cuda_bf16.h>
#include <cstdint>

typedef __nv_bfloat16 bf16;

#define BATCH 2
#define SEQ 2048
#define DMODEL 768
#define NH 12
#define DKH 64
#define MROWS (BATCH*SEQ)

// ---------------- scratch (no allocs allowed) ----------------
__device__ __align__(16) bf16 g_xhi[3u*MROWS*DMODEL];
__device__ __align__(16) bf16 g_xlo[3u*MROWS*DMODEL];
__device__ __align__(16) bf16 g_whi[4u*DMODEL*DMODEL];
__device__ __align__(16) bf16 g_wlo[4u*DMODEL*DMODEL];
__device__ __align__(16) bf16 g_qhi[MROWS*DMODEL];
__device__ __align__(16) bf16 g_qlo[MROWS*DMODEL];
__device__ __align__(16) bf16 g_khi[MROWS*DMODEL];
__device__ __align__(16) bf16 g_klo[MROWS*DMODEL];
__device__ __align__(16) bf16 g_vhi[MROWS*DMODEL];
__device__ __align__(16) bf16 g_vlo[MROWS*DMODEL];
__device__ __align__(16) bf16 g_chi[MROWS*DMODEL];
__device__ __align__(16) bf16 g_clo[MROWS*DMODEL];
__device__ __align__(16) bf16 g_mbias[(size_t)SEQ*SEQ];

// exp(x*0.125 + b) = exp2(x*C + b*LOG2E), C = 0.125*log2(e)
#define SCALE_LOG2E 0.18033688011112042f
#define NEG_BIAS   (-1.4426950408889634e9f)

// ---------------- helpers ----------------
__device__ __forceinline__ uint32_t smem_u32(const void* p) {
    uint32_t a;
    asm("{ .reg .u64 t; cvta.to.shared.u64 t, %1; cvt.u32.u64 %0, t; }" : "=r"(a) : "l"(p));
    return a;
}
__device__ __forceinline__ void ldsm4(uint32_t r[4], uint32_t a) {
    asm volatile("ldmatrix.sync.aligned.m8n8.x4.shared.b16 {%0,%1,%2,%3}, [%4];"
        : "=r"(r[0]), "=r"(r[1]), "=r"(r[2]), "=r"(r[3]) : "r"(a));
}
__device__ __forceinline__ void ldsm4t(uint32_t r[4], uint32_t a) {
    asm volatile("ldmatrix.sync.aligned.m8n8.x4.trans.shared.b16 {%0,%1,%2,%3}, [%4];"
        : "=r"(r[0]), "=r"(r[1]), "=r"(r[2]), "=r"(r[3]) : "r"(a));
}
__device__ __forceinline__ void mma16816(float c[4], uint32_t a0, uint32_t a1, uint32_t a2, uint32_t a3,
                                         uint32_t b0, uint32_t b1) {
    asm volatile("mma.sync.aligned.m16n8k16.row.col.f32.bf16.bf16.f32 "
        "{%0,%1,%2,%3}, {%4,%5,%6,%7}, {%8,%9}, {%0,%1,%2,%3};"
        : "+f"(c[0]), "+f"(c[1]), "+f"(c[2]), "+f"(c[3])
        : "r"(a0), "r"(a1), "r"(a2), "r"(a3), "r"(b0), "r"(b1));
}
__device__ __forceinline__ uint32_t packbf(float x0, float x1) {
    uint32_t r;
    asm("cvt.rn.bf16x2.f32 %0, %1, %2;" : "=r"(r) : "f"(x1), "f"(x0));
    return r;
}
__device__ __forceinline__ void hilo(float v, float& h, float& l) {
    h = __bfloat162float(__float2bfloat16_rn(v));
    l = v - h;
}
// exact truncation split of a pair: hp = {hi(p0),hi(p1)} via PRMT, lp = residuals
__device__ __forceinline__ void splitp(float p0, float p1, uint32_t& hp, uint32_t& lp) {
    uint32_t u0 = __float_as_uint(p0), u1 = __float_as_uint(p1);
    asm("prmt.b32 %0, %1, %2, 0x7632;" : "=r"(hp) : "r"(u0), "r"(u1));
    float h0 = __uint_as_float(u0 & 0xFFFF0000u);
    float h1 = __uint_as_float(u1 & 0xFFFF0000u);
    lp = packbf(p0 - h0, p1 - h1);
}
__device__ __forceinline__ void cpa16(uint32_t s, const void* g) {
    asm volatile("cp.async.cg.shared.global [%0], [%1], 16;" :: "r"(s), "l"(g) : "memory");
}
#define CP_COMMIT() asm volatile("cp.async.commit_group;" ::: "memory")
#define CP_WAIT0()  asm volatile("cp.async.wait_group 0;" ::: "memory")

// ---------------- conversion kernels ----------------
__global__ __launch_bounds__(256) void cvt_in_kernel(
    const float* __restrict__ q, const float* __restrict__ k, const float* __restrict__ v)
{
    const float* src = blockIdx.z == 0 ? q : blockIdx.z == 1 ? k : v;
    bf16* hi = g_xhi + (size_t)blockIdx.z * MROWS * DMODEL;
    bf16* lo = g_xlo + (size_t)blockIdx.z * MROWS * DMODEL;
    size_t i = ((size_t)blockIdx.x * 256 + threadIdx.x) * 4;
    float4 f = *(const float4*)(src + i);
    float h0,l0,h1,l1,h2,l2,h3,l3;
    hilo(f.x,h0,l0); hilo(f.y,h1,l1); hilo(f.z,h2,l2); hilo(f.w,h3,l3);
    *(uint2*)(hi + i) = make_uint2(packbf(f.x, f.y), packbf(f.z, f.w));
    *(uint2*)(lo + i) = make_uint2(packbf(l0, l1), packbf(l2, l3));
}

__global__ __launch_bounds__(256) void cvt_w_kernel(
    const float* __restrict__ wq, const float* __restrict__ wk,
    const float* __restrict__ wv, const float* __restrict__ wo)
{
    const float* src = blockIdx.z == 0 ? wq : blockIdx.z == 1 ? wk : blockIdx.z == 2 ? wv : wo;
    bf16* hi = g_whi + (size_t)blockIdx.z * DMODEL * DMODEL;
    bf16* lo = g_wlo + (size_t)blockIdx.z * DMODEL * DMODEL;
    size_t i = ((size_t)blockIdx.x * 256 + threadIdx.x) * 4;
    float4 f = *(const float4*)(src + i);
    float h0,l0,h1,l1,h2,l2,h3,l3;
    hilo(f.x,h0,l0); hilo(f.y,h1,l1); hilo(f.z,h2,l2); hilo(f.w,h3,l3);
    *(uint2*)(hi + i) = make_uint2(packbf(f.x, f.y), packbf(f.z, f.w));
    *(uint2*)(lo + i) = make_uint2(packbf(l0, l1), packbf(l2, l3));
}

// store mask bias pre-multiplied by log2(e): 0 or -1e9*log2e
__global__ __launch_bounds__(256) void cvt_mask_kernel(const int* __restrict__ mask)
{
    size_t i = ((size_t)blockIdx.x * 256 + threadIdx.x) * 4;
    int4 m = *(const int4*)(mask + i);
    float v0 = m.x ? 0.0f : NEG_BIAS;
    float v1 = m.y ? 0.0f : NEG_BIAS;
    float v2 = m.z ? 0.0f : NEG_BIAS;
    float v3 = m.w ? 0.0f : NEG_BIAS;
    *(uint2*)(g_mbias + i) = make_uint2(packbf(v0, v1), packbf(v2, v3));
}

// ---------------- GEMM (round-6 version: register-buffered sync pipeline) ----------------
#define HS 40                       // smem row stride in halfs (32 + 8 pad)
#define GTB (128*HS*2)              // bytes per tile
#define GEMM_SMEM (4*GTB)           // Ahi, Alo, Bhi, Blo

template<bool OUT>
__global__ __launch_bounds__(256, 1) void gemm_mma_kernel(
    const float* __restrict__ bq, const float* __restrict__ bk,
    const float* __restrict__ bv, const float* __restrict__ bo,
    float* __restrict__ outp)
{
    extern __shared__ char smc[];
    const uint32_t sb = smem_u32(smc);
    const int t = threadIdx.x, lane = t & 31, wid = t >> 5;
    const int wm = wid >> 2, wn = wid & 3;
    const int z = OUT ? 3 : blockIdx.z;

    const bf16 *Ahi, *Alo;
    if (OUT) { Ahi = g_chi; Alo = g_clo; }
    else { Ahi = g_xhi + (size_t)z*MROWS*DMODEL; Alo = g_xlo + (size_t)z*MROWS*DMODEL; }
    const bf16* Bhi = g_whi + (size_t)z*DMODEL*DMODEL;
    const bf16* Blo = g_wlo + (size_t)z*DMODEL*DMODEL;
    const float* bias = OUT ? bo : (z == 0 ? bq : z == 1 ? bk : bv);

    const int bm = blockIdx.y * 128;
    const int bn = blockIdx.x * 128;

    float acc[4][4][4] = {};

    const int lrow0 = t >> 2, lch = t & 3;
    uint4 buf[4][2];

    {
        const bf16* srcs[4] = {Ahi, Alo, Bhi, Blo};
        #pragma unroll
        for (int tt = 0; tt < 4; tt++) {
            int rb = (tt < 2) ? bm : bn;
            #pragma unroll
            for (int u = 0; u < 2; u++)
                buf[tt][u] = *(const uint4*)(srcs[tt] + (size_t)(rb + lrow0 + 64*u)*DMODEL + lch*8);
        }
    }

    for (int c = 0; c < 24; c++) {
        __syncthreads();
        #pragma unroll
        for (int tt = 0; tt < 4; tt++)
            #pragma unroll
            for (int u = 0; u < 2; u++)
                *(uint4*)(smc + tt*GTB + ((lrow0 + 64*u)*HS + lch*8)*2) = buf[tt][u];
        __syncthreads();

        if (c < 23) {
            const int k0 = (c + 1) * 32;
            const bf16* srcs[4] = {Ahi, Alo, Bhi, Blo};
            #pragma unroll
            for (int tt = 0; tt < 4; tt++) {
                int rb = (tt < 2) ? bm : bn;
                #pragma unroll
                for (int u = 0; u < 2; u++)
                    buf[tt][u] = *(const uint4*)(srcs[tt] + (size_t)(rb + lrow0 + 64*u)*DMODEL + k0 + lch*8);
            }
        }

        #pragma unroll
        for (int ks = 0; ks < 2; ks++) {
            uint32_t ah[4][4], al[4][4];
            #pragma unroll
            for (int am = 0; am < 4; am++) {
                uint32_t ad = sb + ((64*wm + 16*am + (lane & 15))*HS + 16*ks + (lane >> 4)*8)*2;
                ldsm4(ah[am], ad);
                ldsm4(al[am], ad + GTB);
            }
            #pragma unroll
            for (int bp = 0; bp < 2; bp++) {
                uint32_t bd = sb + 2*GTB +
                    ((32*wn + 16*bp + (lane & 7) + ((lane >> 4) & 1)*8)*HS + 16*ks + ((lane >> 3) & 1)*8)*2;
                uint32_t bh[4], bl[4];
                ldsm4(bh, bd);
                ldsm4(bl, bd + GTB);
                #pragma unroll
                for (int fi = 0; fi < 2; fi++) {
                    const int bf_ = 2*bp + fi;
                    #pragma unroll
                    for (int am = 0; am < 4; am++) {
                        mma16816(acc[am][bf_], ah[am][0], ah[am][1], ah[am][2], ah[am][3], bh[2*fi], bh[2*fi+1]);
                        mma16816(acc[am][bf_], ah[am][0], ah[am][1], ah[am][2], ah[am][3], bl[2*fi], bl[2*fi+1]);
                        mma16816(acc[am][bf_], al[am][0], al[am][1], al[am][2], al[am][3], bh[2*fi], bh[2*fi+1]);
                    }
                }
            }
        }
    }

    // epilogue
    const int rg = lane >> 2, cq = lane & 3;
    bf16* Dhi = z == 0 ? g_qhi : z == 1 ? g_khi : g_vhi;
    bf16* Dlo = z == 0 ? g_qlo : z == 1 ? g_klo : g_vlo;
    #pragma unroll
    for (int am = 0; am < 4; am++) {
        const int m1 = bm + 64*wm + 16*am + rg;
        const int m2 = m1 + 8;
        #pragma unroll
        for (int bf_ = 0; bf_ < 4; bf_++) {
            const int n = bn + 32*wn + 8*bf_ + 2*cq;
            const float bb0 = bias[n], bb1 = bias[n+1];
            float v00 = acc[am][bf_][0] + bb0, v01 = acc[am][bf_][1] + bb1;
            float v10 = acc[am][bf_][2] + bb0, v11 = acc[am][bf_][3] + bb1;
            if (OUT) {
                *(float2*)(outp + (size_t)m1*DMODEL + n) = make_float2(v00, v01);
                *(float2*)(outp + (size_t)m2*DMODEL + n) = make_float2(v10, v11);
            } else {
                const int hh = n >> 6, d = n & 63;
                const int b1_ = m1 >> 11, s1_ = m1 & (SEQ-1);
                const int b2_ = m2 >> 11, s2_ = m2 & (SEQ-1);
                size_t i1 = ((size_t)(b1_*NH + hh)*SEQ + s1_)*DKH + d;
                size_t i2 = ((size_t)(b2_*NH + hh)*SEQ + s2_)*DKH + d;
                float h0,l0,h1,l1;
                hilo(v00,h0,l0); hilo(v01,h1,l1);
                *(uint32_t*)(Dhi + i1) = packbf(v00, v01);
                *(uint32_t*)(Dlo + i1) = packbf(l0, l1);
                hilo(v10,h0,l0); hilo(v11,h1,l1);
                *(uint32_t*)(Dhi + i2) = packbf(v10, v11);
                *(uint32_t*)(Dlo + i2) = packbf(l0, l1);
            }
        }
    }
}

// ---------------- flash attention: 32 q-rows/warp, 128-q CTA, k-tile 32 ----------------
#define VS 72                          // smem row stride in halfs (64 + 8 pad)
#define QTB (128*VS*2)                 // 18432 B per Q tensor (128 rows)
#define KTB (32*VS*2)                  // 4608 B per KV tensor (32 rows)
#define KVSTG (4*KTB)                  // Khi Klo Vhi Vlo = 18432 B
#define ATTN_SMEM (2*QTB + 2*KVSTG)    // 73728 B

__global__ __launch_bounds__(128, 2) void attn_mma_kernel()
{
    extern __shared__ char smc[];
    const uint32_t sb = smem_u32(smc);
    const uint32_t kvb = sb + 2*QTB;
    const int t = threadIdx.x, lane = t & 31, wid = t >> 5;
    const int rg = lane >> 2, cq = lane & 3;
    const int q0 = blockIdx.x * 128;
    const int h  = blockIdx.y;
    const int b_ = blockIdx.z;
    const size_t headoff = (size_t)(b_*NH + h) * SEQ * DKH;

    auto kvpre = [&](int kt, int s) {
        #pragma unroll
        for (int u = 0; u < 2; u++) {
            int idx = t + 128*u, row = idx >> 3, ch = idx & 7;
            size_t g = headoff + (size_t)(kt*32 + row)*DKH + ch*8;
            uint32_t so = kvb + s*KVSTG + (row*VS + ch*8)*2;
            cpa16(so + 0*KTB, g_khi + g);
            cpa16(so + 1*KTB, g_klo + g);
            cpa16(so + 2*KTB, g_vhi + g);
            cpa16(so + 3*KTB, g_vlo + g);
        }
    };

    kvpre(0, 0); CP_COMMIT();

    // load Q tile (128 rows, hi + lo) once
    #pragma unroll
    for (int u = 0; u < 8; u++) {
        int idx = t + 128*u, row = idx >> 3, ch = idx & 7;
        size_t g = headoff + (size_t)(q0 + row)*DKH + ch*8;
        uint32_t so = (row*VS + ch*8)*2;
        *(uint4*)(smc + 0*QTB + so) = *(const uint4*)(g_qhi + g);
        *(uint4*)(smc + 1*QTB + so) = *(const uint4*)(g_qlo + g);
    }
    __syncthreads();

    // hoist Q fragments: warp owns q rows [32*wid, 32*wid+32) -> 2 m-frags
    uint32_t qh[2][4][4], ql[2][4][4];
    #pragma unroll
    for (int mf = 0; mf < 2; mf++)
        #pragma unroll
        for (int ks = 0; ks < 4; ks++) {
            uint32_t qa = sb + ((32*wid + 16*mf + (lane & 15))*VS + 16*ks + (lane >> 4)*8)*2;
            ldsm4(qh[mf][ks], qa);
            ldsm4(ql[mf][ks], qa + QTB);
        }

    float o[2][8][4] = {};
    float lsum[2][2] = {};

    // mask row base for this warp (row rg of m-frag 0); other rows offset by 8/16/24
    const bf16* mbase = g_mbias + (size_t)(q0 + 32*wid + rg)*SEQ + 2*cq;

    for (int kt = 0; kt < SEQ/32; kt++) {
        CP_WAIT0();
        __syncthreads();
        if (kt < SEQ/32 - 1) { kvpre(kt + 1, (kt + 1) & 1); CP_COMMIT(); }

        const uint32_t stb = kvb + (kt & 1)*KVSTG;

        // S = Q K^T : 32q x 32k per warp
        float s[2][4][4] = {};
        #pragma unroll
        for (int ks = 0; ks < 4; ks++) {
            #pragma unroll
            for (int fp = 0; fp < 2; fp++) {
                uint32_t kd = stb +
                    ((16*fp + (lane & 7) + ((lane >> 4) & 1)*8)*VS + 16*ks + ((lane >> 3) & 1)*8)*2;
                uint32_t kh[4], kl[4];
                ldsm4(kh, kd);
                ldsm4(kl, kd + KTB);
                #pragma unroll
                for (int fi = 0; fi < 2; fi++) {
                    const int f = 2*fp + fi;
                    #pragma unroll
                    for (int mf = 0; mf < 2; mf++) {
                        mma16816(s[mf][f], qh[mf][ks][0], qh[mf][ks][1], qh[mf][ks][2], qh[mf][ks][3], kh[2*fi], kh[2*fi+1]);
                        mma16816(s[mf][f], qh[mf][ks][0], qh[mf][ks][1], qh[mf][ks][2], qh[mf][ks][3], kl[2*fi], kl[2*fi+1]);
                        mma16816(s[mf][f], ql[mf][ks][0], ql[mf][ks][1], ql[mf][ks][2], ql[mf][ks][3], kh[2*fi], kh[2*fi+1]);
                    }
                }
            }
        }

        // p = exp2(raw*C + premultiplied_bias)
        #pragma unroll
        for (int mf = 0; mf < 2; mf++) {
            const bf16* mr1 = mbase + (size_t)(16*mf)*SEQ + kt*32;
            const bf16* mr2 = mr1 + (size_t)8*SEQ;
            #pragma unroll
            for (int f = 0; f < 4; f++) {
                __nv_bfloat162 u1 = *(const __nv_bfloat162*)(mr1 + 8*f);
                __nv_bfloat162 u2 = *(const __nv_bfloat162*)(mr2 + 8*f);
                s[mf][f][0] = exp2f(fmaf(s[mf][f][0], SCALE_LOG2E, __low2float(u1)));
                s[mf][f][1] = exp2f(fmaf(s[mf][f][1], SCALE_LOG2E, __high2float(u1)));
                s[mf][f][2] = exp2f(fmaf(s[mf][f][2], SCALE_LOG2E, __low2float(u2)));
                s[mf][f][3] = exp2f(fmaf(s[mf][f][3], SCALE_LOG2E, __high2float(u2)));
                lsum[mf][0] += s[mf][f][0] + s[mf][f][1];
                lsum[mf][1] += s[mf][f][2] + s[mf][f][3];
            }
        }

        // O += P @ V : V frags loaded once, reused across both m-frags
        #pragma unroll
        for (int kk = 0; kk < 2; kk++) {
            uint32_t ph[2][4], pl[2][4];
            #pragma unroll
            for (int mf = 0; mf < 2; mf++) {
                float* p = s[mf][2*kk];
                float* q = s[mf][2*kk+1];
                splitp(p[0], p[1], ph[mf][0], pl[mf][0]);
                splitp(p[2], p[3], ph[mf][1], pl[mf][1]);
                splitp(q[0], q[1], ph[mf][2], pl[mf][2]);
                splitp(q[2], q[3], ph[mf][3], pl[mf][3]);
            }
            #pragma unroll
            for (int dg = 0; dg < 4; dg++) {
                uint32_t vd = stb + 2*KTB + ((16*kk + (lane & 15))*VS + 16*dg + (lane >> 4)*8)*2;
                uint32_t vh[4], vl[4];
                ldsm4t(vh, vd);
                ldsm4t(vl, vd + KTB);
                #pragma unroll
                for (int fi = 0; fi < 2; fi++) {
                    const int df = 2*dg + fi;
                    #pragma unroll
                    for (int mf = 0; mf < 2; mf++) {
                        mma16816(o[mf][df], ph[mf][0], ph[mf][1], ph[mf][2], ph[mf][3], vh[2*fi], vh[2*fi+1]);
                        mma16816(o[mf][df], ph[mf][0], ph[mf][1], ph[mf][2], ph[mf][3], vl[2*fi], vl[2*fi+1]);
                        mma16816(o[mf][df], pl[mf][0], pl[mf][1], pl[mf][2], pl[mf][3], vh[2*fi], vh[2*fi+1]);
                    }
                }
            }
        }
    }

    // final reduction of row sums across quad lanes
    #pragma unroll
    for (int mf = 0; mf < 2; mf++) {
        lsum[mf][0] += __shfl_xor_sync(0xffffffffu, lsum[mf][0], 1);
        lsum[mf][0] += __shfl_xor_sync(0xffffffffu, lsum[mf][0], 2);
        lsum[mf][1] += __shfl_xor_sync(0xffffffffu, lsum[mf][1], 1);
        lsum[mf][1] += __shfl_xor_sync(0xffffffffu, lsum[mf][1], 2);
    }

    // epilogue: normalize, split hi/lo, write ctx
    #pragma unroll
    for (int mf = 0; mf < 2; mf++) {
        const float inv1 = 1.0f / lsum[mf][0], inv2 = 1.0f / lsum[mf][1];
        const int gr = q0 + 32*wid + 16*mf + rg;
        size_t base1 = ((size_t)b_*SEQ + gr)*DMODEL + h*DKH;
        size_t base2 = base1 + (size_t)8*DMODEL;
        #pragma unroll
        for (int df = 0; df < 8; df++) {
            const int d0 = 8*df + 2*cq;
            float v0 = o[mf][df][0]*inv1, v1 = o[mf][df][1]*inv1;
            float v2 = o[mf][df][2]*inv2, v3 = o[mf][df][3]*inv2;
            float h0,l0,h1,l1v;
            hilo(v0,h0,l0); hilo(v1,h1,l1v);
            *(uint32_t*)(g_chi + base1 + d0) = packbf(v0, v1);
            *(uint32_t*)(g_clo + base1 + d0) = packbf(l0, l1v);
            hilo(v2,h0,l0); hilo(v3,h1,l1v);
            *(uint32_t*)(g_chi + base2 + d0) = packbf(v2, v3);
            *(uint32_t*)(g_clo + base2 + d0) = packbf(l0, l1v);
        }
    }
}

// ---------------- launcher ----------------
extern "C" void kernel_launch(void* const* d_in, const int* in_sizes, int n_in,
                              void* d_out, int out_size)
{
    const float* q   = (const float*)d_in[0];
    const float* k   = (const float*)d_in[1];
    const float* v   = (const float*)d_in[2];
    const int*   msk = (const int*)  d_in[3];
    const float* w_q = (const float*)d_in[4];
    const float* b_q = (const float*)d_in[5];
    const float* w_k = (const float*)d_in[6];
    const float* b_k = (const float*)d_in[7];
    const float* w_v = (const float*)d_in[8];
    const float* b_v = (const float*)d_in[9];
    const float* w_o = (const float*)d_in[10];
    const float* b_o = (const float*)d_in[11];
    float* out = (float*)d_out;

    cudaFuncSetAttribute(gemm_mma_kernel<false>, cudaFuncAttributeMaxDynamicSharedMemorySize, GEMM_SMEM);
    cudaFuncSetAttribute(gemm_mma_kernel<true>,  cudaFuncAttributeMaxDynamicSharedMemorySize, GEMM_SMEM);
    cudaFuncSetAttribute(attn_mma_kernel, cudaFuncAttributeMaxDynamicSharedMemorySize, ATTN_SMEM);

    cvt_in_kernel<<<dim3(MROWS*DMODEL/1024, 1, 3), 256>>>(q, k, v);
    cvt_w_kernel<<<dim3(DMODEL*DMODEL/1024, 1, 4), 256>>>(w_q, w_k, w_v, w_o);
    cvt_mask_kernel<<<dim3((size_t)SEQ*SEQ/1024, 1, 1), 256>>>(msk);
    gemm_mma_kernel<false><<<dim3(DMODEL/128, MROWS/128, 3), 256, GEMM_SMEM>>>(b_q, b_k, b_v, b_o, out);
    attn_mma_kernel<<<dim3(SEQ/128, NH, BATCH), 128, ATTN_SMEM>>>();
    gemm_mma_kernel<true><<<dim3(DMODEL/128, MROWS/128, 1), 256, GEMM_SMEM>>>(b_q, b_k, b_v, b_o, out);
}

// round 12
// speedup vs baseline: 1.0686x; 1.0133x over previous
#include <cuda_runtime.h>
#include <cuda_bf16.h>
#include <cstdint>

typedef __nv_bfloat16 bf16;

#define BATCH 2
#define SEQ 2048
#define DMODEL 768
#define NH 12
#define DKH 64
#define MROWS (BATCH*SEQ)

// ---------------- scratch (no allocs allowed) ----------------
__device__ __align__(16) bf16 g_xhi[3u*MROWS*DMODEL];
__device__ __align__(16) bf16 g_xlo[3u*MROWS*DMODEL];
__device__ __align__(16) bf16 g_whi[4u*DMODEL*DMODEL];
__device__ __align__(16) bf16 g_wlo[4u*DMODEL*DMODEL];
__device__ __align__(16) bf16 g_qhi[MROWS*DMODEL];
__device__ __align__(16) bf16 g_qlo[MROWS*DMODEL];
__device__ __align__(16) bf16 g_khi[MROWS*DMODEL];
__device__ __align__(16) bf16 g_klo[MROWS*DMODEL];
__device__ __align__(16) bf16 g_vhi[MROWS*DMODEL];
__device__ __align__(16) bf16 g_vlo[MROWS*DMODEL];
__device__ __align__(16) bf16 g_chi[MROWS*DMODEL];
__device__ __align__(16) bf16 g_clo[MROWS*DMODEL];
__device__ __align__(16) bf16 g_mbias[(size_t)SEQ*SEQ];

// exp(x*0.125 + b) = exp2(x*C + b*LOG2E), C = 0.125*log2(e)
#define SCALE_LOG2E 0.18033688011112042f
#define NEG_BIAS   (-1.4426950408889634e9f)

// ---------------- helpers ----------------
__device__ __forceinline__ uint32_t smem_u32(const void* p) {
    uint32_t a;
    asm("{ .reg .u64 t; cvta.to.shared.u64 t, %1; cvt.u32.u64 %0, t; }" : "=r"(a) : "l"(p));
    return a;
}
__device__ __forceinline__ void ldsm4(uint32_t r[4], uint32_t a) {
    asm volatile("ldmatrix.sync.aligned.m8n8.x4.shared.b16 {%0,%1,%2,%3}, [%4];"
        : "=r"(r[0]), "=r"(r[1]), "=r"(r[2]), "=r"(r[3]) : "r"(a));
}
__device__ __forceinline__ void ldsm4t(uint32_t r[4], uint32_t a) {
    asm volatile("ldmatrix.sync.aligned.m8n8.x4.trans.shared.b16 {%0,%1,%2,%3}, [%4];"
        : "=r"(r[0]), "=r"(r[1]), "=r"(r[2]), "=r"(r[3]) : "r"(a));
}
__device__ __forceinline__ void mma16816(float c[4], uint32_t a0, uint32_t a1, uint32_t a2, uint32_t a3,
                                         uint32_t b0, uint32_t b1) {
    asm volatile("mma.sync.aligned.m16n8k16.row.col.f32.bf16.bf16.f32 "
        "{%0,%1,%2,%3}, {%4,%5,%6,%7}, {%8,%9}, {%0,%1,%2,%3};"
        : "+f"(c[0]), "+f"(c[1]), "+f"(c[2]), "+f"(c[3])
        : "r"(a0), "r"(a1), "r"(a2), "r"(a3), "r"(b0), "r"(b1));
}
__device__ __forceinline__ uint32_t packbf(float x0, float x1) {
    uint32_t r;
    asm("cvt.rn.bf16x2.f32 %0, %1, %2;" : "=r"(r) : "f"(x1), "f"(x0));
    return r;
}
__device__ __forceinline__ void hilo(float v, float& h, float& l) {
    h = __bfloat162float(__float2bfloat16_rn(v));
    l = v - h;
}
// exact truncation split of a pair: hp = {hi(p0),hi(p1)} via PRMT, lp = residuals
__device__ __forceinline__ void splitp(float p0, float p1, uint32_t& hp, uint32_t& lp) {
    uint32_t u0 = __float_as_uint(p0), u1 = __float_as_uint(p1);
    asm("prmt.b32 %0, %1, %2, 0x7632;" : "=r"(hp) : "r"(u0), "r"(u1));
    float h0 = __uint_as_float(u0 & 0xFFFF0000u);
    float h1 = __uint_as_float(u1 & 0xFFFF0000u);
    lp = packbf(p0 - h0, p1 - h1);
}
__device__ __forceinline__ void cpa16(uint32_t s, const void* g) {
    asm volatile("cp.async.cg.shared.global [%0], [%1], 16;" :: "r"(s), "l"(g) : "memory");
}
#define CP_COMMIT() asm volatile("cp.async.commit_group;" ::: "memory")
#define CP_WAIT0()  asm volatile("cp.async.wait_group 0;" ::: "memory")

// ---------------- conversion kernels ----------------
__global__ __launch_bounds__(256) void cvt_in_kernel(
    const float* __restrict__ q, const float* __restrict__ k, const float* __restrict__ v)
{
    const float* src = blockIdx.z == 0 ? q : blockIdx.z == 1 ? k : v;
    bf16* hi = g_xhi + (size_t)blockIdx.z * MROWS * DMODEL;
    bf16* lo = g_xlo + (size_t)blockIdx.z * MROWS * DMODEL;
    size_t i = ((size_t)blockIdx.x * 256 + threadIdx.x) * 4;
    float4 f = *(const float4*)(src + i);
    float h0,l0,h1,l1,h2,l2,h3,l3;
    hilo(f.x,h0,l0); hilo(f.y,h1,l1); hilo(f.z,h2,l2); hilo(f.w,h3,l3);
    *(uint2*)(hi + i) = make_uint2(packbf(f.x, f.y), packbf(f.z, f.w));
    *(uint2*)(lo + i) = make_uint2(packbf(l0, l1), packbf(l2, l3));
}

__global__ __launch_bounds__(256) void cvt_w_kernel(
    const float* __restrict__ wq, const float* __restrict__ wk,
    const float* __restrict__ wv, const float* __restrict__ wo)
{
    const float* src = blockIdx.z == 0 ? wq : blockIdx.z == 1 ? wk : blockIdx.z == 2 ? wv : wo;
    bf16* hi = g_whi + (size_t)blockIdx.z * DMODEL * DMODEL;
    bf16* lo = g_wlo + (size_t)blockIdx.z * DMODEL * DMODEL;
    size_t i = ((size_t)blockIdx.x * 256 + threadIdx.x) * 4;
    float4 f = *(const float4*)(src + i);
    float h0,l0,h1,l1,h2,l2,h3,l3;
    hilo(f.x,h0,l0); hilo(f.y,h1,l1); hilo(f.z,h2,l2); hilo(f.w,h3,l3);
    *(uint2*)(hi + i) = make_uint2(packbf(f.x, f.y), packbf(f.z, f.w));
    *(uint2*)(lo + i) = make_uint2(packbf(l0, l1), packbf(l2, l3));
}

// store mask bias pre-multiplied by log2(e): 0 or -1e9*log2e
__global__ __launch_bounds__(256) void cvt_mask_kernel(const int* __restrict__ mask)
{
    size_t i = ((size_t)blockIdx.x * 256 + threadIdx.x) * 4;
    int4 m = *(const int4*)(mask + i);
    float v0 = m.x ? 0.0f : NEG_BIAS;
    float v1 = m.y ? 0.0f : NEG_BIAS;
    float v2 = m.z ? 0.0f : NEG_BIAS;
    float v3 = m.w ? 0.0f : NEG_BIAS;
    *(uint2*)(g_mbias + i) = make_uint2(packbf(v0, v1), packbf(v2, v3));
}

// ---------------- GEMM: 256x128 CTA tile, 64x64 warp tiles, r6 sync pipeline ----------------
#define HS 40                        // smem row stride in halfs (32 + 8 pad)
#define ATB_G (256*HS*2)             // A tensor bytes (20480)
#define BTB_G (128*HS*2)             // B tensor bytes (10240)
#define GEMM_SMEM (2*ATB_G + 2*BTB_G)  // 61440

template<bool OUT>
__global__ __launch_bounds__(256, 1) void gemm_mma_kernel(
    const float* __restrict__ bq, const float* __restrict__ bk,
    const float* __restrict__ bv, const float* __restrict__ bo,
    float* __restrict__ outp)
{
    extern __shared__ char smc[];
    const uint32_t sb = smem_u32(smc);
    const int t = threadIdx.x, lane = t & 31, wid = t >> 5;
    const int wm = wid >> 1, wn = wid & 1;    // 4 x 2 warp grid, 64x64 tiles
    const int z = OUT ? 3 : blockIdx.z;

    const bf16 *Ahi, *Alo;
    if (OUT) { Ahi = g_chi; Alo = g_clo; }
    else { Ahi = g_xhi + (size_t)z*MROWS*DMODEL; Alo = g_xlo + (size_t)z*MROWS*DMODEL; }
    const bf16* Bhi = g_whi + (size_t)z*DMODEL*DMODEL;
    const bf16* Blo = g_wlo + (size_t)z*DMODEL*DMODEL;
    const float* bias = OUT ? bo : (z == 0 ? bq : z == 1 ? bk : bv);

    const int bm = blockIdx.y * 256;
    const int bn = blockIdx.x * 128;

    float acc[4][8][4] = {};

    // loaders: A 256x32 (4 uint4/thread/tensor), B 128x32 (2 uint4/thread/tensor)
    const int arow = t >> 2, ac8 = (t & 3) * 8;     // A: rows t>>2 + 64u
    uint4 bufAh[4], bufAl[4], bufBh[2], bufBl[2];

    auto ldg_chunk = [&](int k0) {
        #pragma unroll
        for (int u = 0; u < 4; u++) {
            size_t off = (size_t)(bm + arow + 64*u)*DMODEL + k0 + ac8;
            bufAh[u] = *(const uint4*)(Ahi + off);
            bufAl[u] = *(const uint4*)(Alo + off);
        }
        #pragma unroll
        for (int u = 0; u < 2; u++) {
            size_t off = (size_t)(bn + arow + 64*u)*DMODEL + k0 + ac8;
            bufBh[u] = *(const uint4*)(Bhi + off);
            bufBl[u] = *(const uint4*)(Blo + off);
        }
    };
    auto sts_chunk = [&]() {
        #pragma unroll
        for (int u = 0; u < 4; u++) {
            uint32_t so = ((arow + 64*u)*HS + ac8)*2;
            *(uint4*)(smc + so) = bufAh[u];
            *(uint4*)(smc + ATB_G + so) = bufAl[u];
        }
        #pragma unroll
        for (int u = 0; u < 2; u++) {
            uint32_t so = ((arow + 64*u)*HS + ac8)*2;
            *(uint4*)(smc + 2*ATB_G + so) = bufBh[u];
            *(uint4*)(smc + 2*ATB_G + BTB_G + so) = bufBl[u];
        }
    };

    ldg_chunk(0);

    for (int c = 0; c < 24; c++) {
        __syncthreads();
        sts_chunk();
        __syncthreads();
        if (c < 23) ldg_chunk((c + 1) * 32);

        #pragma unroll
        for (int ks = 0; ks < 2; ks++) {
            uint32_t ah[4][4], al[4][4];
            #pragma unroll
            for (int am = 0; am < 4; am++) {
                uint32_t ad = sb + ((64*wm + 16*am + (lane & 15))*HS + 16*ks + (lane >> 4)*8)*2;
                ldsm4(ah[am], ad);
                ldsm4(al[am], ad + ATB_G);
            }
            #pragma unroll
            for (int bp = 0; bp < 4; bp++) {
                uint32_t bd = sb + 2*ATB_G +
                    ((64*wn + 16*bp + (lane & 7) + ((lane >> 4) & 1)*8)*HS + 16*ks + ((lane >> 3) & 1)*8)*2;
                uint32_t bh[4], bl[4];
                ldsm4(bh, bd);
                ldsm4(bl, bd + BTB_G);
                #pragma unroll
                for (int fi = 0; fi < 2; fi++) {
                    const int nf = 2*bp + fi;
                    #pragma unroll
                    for (int am = 0; am < 4; am++) {
                        mma16816(acc[am][nf], ah[am][0], ah[am][1], ah[am][2], ah[am][3], bh[2*fi], bh[2*fi+1]);
                        mma16816(acc[am][nf], ah[am][0], ah[am][1], ah[am][2], ah[am][3], bl[2*fi], bl[2*fi+1]);
                        mma16816(acc[am][nf], al[am][0], al[am][1], al[am][2], al[am][3], bh[2*fi], bh[2*fi+1]);
                    }
                }
            }
        }
    }

    // epilogue
    const int rg = lane >> 2, cq = lane & 3;
    bf16* Dhi = z == 0 ? g_qhi : z == 1 ? g_khi : g_vhi;
    bf16* Dlo = z == 0 ? g_qlo : z == 1 ? g_klo : g_vlo;
    #pragma unroll
    for (int am = 0; am < 4; am++) {
        const int m1 = bm + 64*wm + 16*am + rg;
        const int m2 = m1 + 8;
        #pragma unroll
        for (int nf = 0; nf < 8; nf++) {
            const int n = bn + 64*wn + 8*nf + 2*cq;
            const float bb0 = bias[n], bb1 = bias[n+1];
            float v00 = acc[am][nf][0] + bb0, v01 = acc[am][nf][1] + bb1;
            float v10 = acc[am][nf][2] + bb0, v11 = acc[am][nf][3] + bb1;
            if (OUT) {
                *(float2*)(outp + (size_t)m1*DMODEL + n) = make_float2(v00, v01);
                *(float2*)(outp + (size_t)m2*DMODEL + n) = make_float2(v10, v11);
            } else {
                const int hh = n >> 6, d = n & 63;
                const int b1_ = m1 >> 11, s1_ = m1 & (SEQ-1);
                const int b2_ = m2 >> 11, s2_ = m2 & (SEQ-1);
                size_t i1 = ((size_t)(b1_*NH + hh)*SEQ + s1_)*DKH + d;
                size_t i2 = ((size_t)(b2_*NH + hh)*SEQ + s2_)*DKH + d;
                float h0,l0,h1,l1;
                hilo(v00,h0,l0); hilo(v01,h1,l1);
                *(uint32_t*)(Dhi + i1) = packbf(v00, v01);
                *(uint32_t*)(Dlo + i1) = packbf(l0, l1);
                hilo(v10,h0,l0); hilo(v11,h1,l1);
                *(uint32_t*)(Dhi + i2) = packbf(v10, v11);
                *(uint32_t*)(Dlo + i2) = packbf(l0, l1);
            }
        }
    }
}

// ---------------- flash attention: 32 q-rows/warp, 128-q CTA, k-tile 32 ----------------
#define VS 72                          // smem row stride in halfs (64 + 8 pad)
#define QTB (128*VS*2)                 // 18432 B per Q tensor (128 rows)
#define KTB (32*VS*2)                  // 4608 B per KV tensor (32 rows)
#define KVSTG (4*KTB)                  // Khi Klo Vhi Vlo = 18432 B
#define ATTN_SMEM (2*QTB + 2*KVSTG)    // 73728 B

__global__ __launch_bounds__(128, 2) void attn_mma_kernel()
{
    extern __shared__ char smc[];
    const uint32_t sb = smem_u32(smc);
    const uint32_t kvb = sb + 2*QTB;
    const int t = threadIdx.x, lane = t & 31, wid = t >> 5;
    const int rg = lane >> 2, cq = lane & 3;
    const int q0 = blockIdx.x * 128;
    const int h  = blockIdx.y;
    const int b_ = blockIdx.z;
    const size_t headoff = (size_t)(b_*NH + h) * SEQ * DKH;

    auto kvpre = [&](int kt, int s) {
        #pragma unroll
        for (int u = 0; u < 2; u++) {
            int idx = t + 128*u, row = idx >> 3, ch = idx & 7;
            size_t g = headoff + (size_t)(kt*32 + row)*DKH + ch*8;
            uint32_t so = kvb + s*KVSTG + (row*VS + ch*8)*2;
            cpa16(so + 0*KTB, g_khi + g);
            cpa16(so + 1*KTB, g_klo + g);
            cpa16(so + 2*KTB, g_vhi + g);
            cpa16(so + 3*KTB, g_vlo + g);
        }
    };

    kvpre(0, 0); CP_COMMIT();

    // load Q tile (128 rows, hi + lo) once
    #pragma unroll
    for (int u = 0; u < 8; u++) {
        int idx = t + 128*u, row = idx >> 3, ch = idx & 7;
        size_t g = headoff + (size_t)(q0 + row)*DKH + ch*8;
        uint32_t so = (row*VS + ch*8)*2;
        *(uint4*)(smc + 0*QTB + so) = *(const uint4*)(g_qhi + g);
        *(uint4*)(smc + 1*QTB + so) = *(const uint4*)(g_qlo + g);
    }
    __syncthreads();

    // hoist Q fragments: warp owns q rows [32*wid, 32*wid+32) -> 2 m-frags
    uint32_t qh[2][4][4], ql[2][4][4];
    #pragma unroll
    for (int mf = 0; mf < 2; mf++)
        #pragma unroll
        for (int ks = 0; ks < 4; ks++) {
            uint32_t qa = sb + ((32*wid + 16*mf + (lane & 15))*VS + 16*ks + (lane >> 4)*8)*2;
            ldsm4(qh[mf][ks], qa);
            ldsm4(ql[mf][ks], qa + QTB);
        }

    float o[2][8][4] = {};
    float lsum[2][2] = {};

    const bf16* mbase = g_mbias + (size_t)(q0 + 32*wid + rg)*SEQ + 2*cq;

    for (int kt = 0; kt < SEQ/32; kt++) {
        CP_WAIT0();
        __syncthreads();
        if (kt < SEQ/32 - 1) { kvpre(kt + 1, (kt + 1) & 1); CP_COMMIT(); }

        const uint32_t stb = kvb + (kt & 1)*KVSTG;

        // S = Q K^T : 32q x 32k per warp
        float s[2][4][4] = {};
        #pragma unroll
        for (int ks = 0; ks < 4; ks++) {
            #pragma unroll
            for (int fp = 0; fp < 2; fp++) {
                uint32_t kd = stb +
                    ((16*fp + (lane & 7) + ((lane >> 4) & 1)*8)*VS + 16*ks + ((lane >> 3) & 1)*8)*2;
                uint32_t kh[4], kl[4];
                ldsm4(kh, kd);
                ldsm4(kl, kd + KTB);
                #pragma unroll
                for (int fi = 0; fi < 2; fi++) {
                    const int f = 2*fp + fi;
                    #pragma unroll
                    for (int mf = 0; mf < 2; mf++) {
                        mma16816(s[mf][f], qh[mf][ks][0], qh[mf][ks][1], qh[mf][ks][2], qh[mf][ks][3], kh[2*fi], kh[2*fi+1]);
                        mma16816(s[mf][f], qh[mf][ks][0], qh[mf][ks][1], qh[mf][ks][2], qh[mf][ks][3], kl[2*fi], kl[2*fi+1]);
                        mma16816(s[mf][f], ql[mf][ks][0], ql[mf][ks][1], ql[mf][ks][2], ql[mf][ks][3], kh[2*fi], kh[2*fi+1]);
                    }
                }
            }
        }

        // p = exp2(raw*C + premultiplied_bias)
        #pragma unroll
        for (int mf = 0; mf < 2; mf++) {
            const bf16* mr1 = mbase + (size_t)(16*mf)*SEQ + kt*32;
            const bf16* mr2 = mr1 + (size_t)8*SEQ;
            #pragma unroll
            for (int f = 0; f < 4; f++) {
                __nv_bfloat162 u1 = *(const __nv_bfloat162*)(mr1 + 8*f);
                __nv_bfloat162 u2 = *(const __nv_bfloat162*)(mr2 + 8*f);
                s[mf][f][0] = exp2f(fmaf(s[mf][f][0], SCALE_LOG2E, __low2float(u1)));
                s[mf][f][1] = exp2f(fmaf(s[mf][f][1], SCALE_LOG2E, __high2float(u1)));
                s[mf][f][2] = exp2f(fmaf(s[mf][f][2], SCALE_LOG2E, __low2float(u2)));
                s[mf][f][3] = exp2f(fmaf(s[mf][f][3], SCALE_LOG2E, __high2float(u2)));
                lsum[mf][0] += s[mf][f][0] + s[mf][f][1];
                lsum[mf][1] += s[mf][f][2] + s[mf][f][3];
            }
        }

        // O += P @ V : V frags loaded once, reused across both m-frags
        #pragma unroll
        for (int kk = 0; kk < 2; kk++) {
            uint32_t ph[2][4], pl[2][4];
            #pragma unroll
            for (int mf = 0; mf < 2; mf++) {
                float* p = s[mf][2*kk];
                float* q = s[mf][2*kk+1];
                splitp(p[0], p[1], ph[mf][0], pl[mf][0]);
                splitp(p[2], p[3], ph[mf][1], pl[mf][1]);
                splitp(q[0], q[1], ph[mf][2], pl[mf][2]);
                splitp(q[2], q[3], ph[mf][3], pl[mf][3]);
            }
            #pragma unroll
            for (int dg = 0; dg < 4; dg++) {
                uint32_t vd = stb + 2*KTB + ((16*kk + (lane & 15))*VS + 16*dg + (lane >> 4)*8)*2;
                uint32_t vh[4], vl[4];
                ldsm4t(vh, vd);
                ldsm4t(vl, vd + KTB);
                #pragma unroll
                for (int fi = 0; fi < 2; fi++) {
                    const int df = 2*dg + fi;
                    #pragma unroll
                    for (int mf = 0; mf < 2; mf++) {
                        mma16816(o[mf][df], ph[mf][0], ph[mf][1], ph[mf][2], ph[mf][3], vh[2*fi], vh[2*fi+1]);
                        mma16816(o[mf][df], ph[mf][0], ph[mf][1], ph[mf][2], ph[mf][3], vl[2*fi], vl[2*fi+1]);
                        mma16816(o[mf][df], pl[mf][0], pl[mf][1], pl[mf][2], pl[mf][3], vh[2*fi], vh[2*fi+1]);
                    }
                }
            }
        }
    }

    // final reduction of row sums across quad lanes
    #pragma unroll
    for (int mf = 0; mf < 2; mf++) {
        lsum[mf][0] += __shfl_xor_sync(0xffffffffu, lsum[mf][0], 1);
        lsum[mf][0] += __shfl_xor_sync(0xffffffffu, lsum[mf][0], 2);
        lsum[mf][1] += __shfl_xor_sync(0xffffffffu, lsum[mf][1], 1);
        lsum[mf][1] += __shfl_xor_sync(0xffffffffu, lsum[mf][1], 2);
    }

    // epilogue: normalize, split hi/lo, write ctx
    #pragma unroll
    for (int mf = 0; mf < 2; mf++) {
        const float inv1 = 1.0f / lsum[mf][0], inv2 = 1.0f / lsum[mf][1];
        const int gr = q0 + 32*wid + 16*mf + rg;
        size_t base1 = ((size_t)b_*SEQ + gr)*DMODEL + h*DKH;
        size_t base2 = base1 + (size_t)8*DMODEL;
        #pragma unroll
        for (int df = 0; df < 8; df++) {
            const int d0 = 8*df + 2*cq;
            float v0 = o[mf][df][0]*inv1, v1 = o[mf][df][1]*inv1;
            float v2 = o[mf][df][2]*inv2, v3 = o[mf][df][3]*inv2;
            float h0,l0,h1,l1v;
            hilo(v0,h0,l0); hilo(v1,h1,l1v);
            *(uint32_t*)(g_chi + base1 + d0) = packbf(v0, v1);
            *(uint32_t*)(g_clo + base1 + d0) = packbf(l0, l1v);
            hilo(v2,h0,l0); hilo(v3,h1,l1v);
            *(uint32_t*)(g_chi + base2 + d0) = packbf(v2, v3);
            *(uint32_t*)(g_clo + base2 + d0) = packbf(l0, l1v);
        }
    }
}

// ---------------- launcher ----------------
extern "C" void kernel_launch(void* const* d_in, const int* in_sizes, int n_in,
                              void* d_out, int out_size)
{
    const float* q   = (const float*)d_in[0];
    const float* k   = (const float*)d_in[1];
    const float* v   = (const float*)d_in[2];
    const int*   msk = (const int*)  d_in[3];
    const float* w_q = (const float*)d_in[4];
    const float* b_q = (const float*)d_in[5];
    const float* w_k = (const float*)d_in[6];
    const float* b_k = (const float*)d_in[7];
    const float* w_v = (const float*)d_in[8];
    const float* b_v = (const float*)d_in[9];
    const float* w_o = (const float*)d_in[10];
    const float* b_o = (const float*)d_in[11];
    float* out = (float*)d_out;

    cudaFuncSetAttribute(gemm_mma_kernel<false>, cudaFuncAttributeMaxDynamicSharedMemorySize, GEMM_SMEM);
    cudaFuncSetAttribute(gemm_mma_kernel<true>,  cudaFuncAttributeMaxDynamicSharedMemorySize, GEMM_SMEM);
    cudaFuncSetAttribute(attn_mma_kernel, cudaFuncAttributeMaxDynamicSharedMemorySize, ATTN_SMEM);

    cvt_in_kernel<<<dim3(MROWS*DMODEL/1024, 1, 3), 256>>>(q, k, v);
    cvt_w_kernel<<<dim3(DMODEL*DMODEL/1024, 1, 4), 256>>>(w_q, w_k, w_v, w_o);
    cvt_mask_kernel<<<dim3((size_t)SEQ*SEQ/1024, 1, 1), 256>>>(msk);
    gemm_mma_kernel<false><<<dim3(DMODEL/128, MROWS/256, 3), 256, GEMM_SMEM>>>(b_q, b_k, b_v, b_o, out);
    attn_mma_kernel<<<dim3(SEQ/128, NH, BATCH), 128, ATTN_SMEM>>>();
    gemm_mma_kernel<true><<<dim3(DMODEL/128, MROWS/256, 1), 256, GEMM_SMEM>>>(b_q, b_k, b_v, b_o, out);
}